// round 4
// baseline (speedup 1.0000x reference)
#include <cuda_runtime.h>

// Column-wise L2 normalization: u[d] = sum_n x[n,d]^2 + eps; out = x * rsqrt(u)
// x: [32768, 2048] fp32 row-major.
//
// Strategy: persistent kernel, 4 column stripes of 512 cols (64 MB each, fits
// in GB300's ~126 MB L2). Per stripe: phase A reduces (input cached in L2),
// software grid barrier, phase B re-reads (L2 hits) and writes with .cs
// streaming hints. DRAM traffic ~512 MB instead of the naive 768 MB.

#define NCTAS     148
#define TPB       512
#define DV        512            // D/4 (float4 per full row)
#define NROWS     32768
#define NSTRIPES  4
#define SCOLS     512            // columns per stripe
#define SVEC      128            // float4 groups per stripe row
#define ROWSTRIDE (4 * NCTAS)    // 592: 4 row-phases per block iteration

__device__ float g_partial[NCTAS * SCOLS];   // per-CTA column partial sums
__device__ unsigned int g_bar_count;         // zero-initialized at load
__device__ unsigned int g_bar_gen;           // monotonically increasing (wrap-safe)

// Self-resetting grid barrier. Requires all NCTAS CTAs co-resident
// (148 CTAs <= 148/152 SMs at 1 CTA/SM with these resources).
__device__ __forceinline__ void grid_barrier() {
    __threadfence();        // make this thread's prior global stores visible
    __syncthreads();
    if (threadIdx.x == 0) {
        // Read current generation BEFORE arriving. Safe: the current barrier
        // cannot complete (gen cannot advance) until this CTA arrives.
        unsigned int target = *(volatile unsigned int*)&g_bar_gen + 1u;
        unsigned int arrived = atomicAdd(&g_bar_count, 1u);
        if (arrived == NCTAS - 1) {
            atomicExch(&g_bar_count, 0u);   // reset before releasing
            __threadfence();
            atomicAdd(&g_bar_gen, 1u);
        } else {
            while ((int)(*(volatile unsigned int*)&g_bar_gen - target) < 0)
                __nanosleep(64);
        }
        __threadfence();
    }
    __syncthreads();
}

__global__ __launch_bounds__(TPB, 1)
void colnorm_kernel(const float* __restrict__ x, float* __restrict__ out) {
    const int tid    = threadIdx.x;
    const int b      = blockIdx.x;
    const int col4   = tid & (SVEC - 1);   // float4 group within stripe (0..127)
    const int rphase = tid >> 7;           // row phase (0..3)
    const int r0     = b + rphase * NCTAS; // first row for this thread

    __shared__ float4 sred[4 * SVEC];      // 8 KB: per-rowphase partials
    __shared__ float  sinv[SCOLS];         // 2 KB: rsqrt per stripe column

    const float4* __restrict__ x4 = (const float4*)x;
    float4* __restrict__       o4 = (float4*)out;

    for (int s = 0; s < NSTRIPES; ++s) {
        const int base = s * SVEC + col4;  // float4 index within a row

        // ---- Phase A: per-CTA column sum-of-squares over this stripe ----
        float4 acc = make_float4(0.f, 0.f, 0.f, 0.f);
        #pragma unroll 4
        for (int r = r0; r < NROWS; r += ROWSTRIDE) {
            float4 v = x4[r * DV + base];          // default .ca load -> fills L2
            acc.x += v.x * v.x;
            acc.y += v.y * v.y;
            acc.z += v.z * v.z;
            acc.w += v.w * v.w;
        }
        sred[rphase * SVEC + col4] = acc;
        __syncthreads();
        {
            // Fold the 4 row phases; tid indexes stripe-local column 0..511.
            const float* sf = (const float*)sred;
            g_partial[b * SCOLS + tid] =
                sf[tid] + sf[SCOLS + tid] + sf[2 * SCOLS + tid] + sf[3 * SCOLS + tid];
        }
        grid_barrier();

        // ---- Phase B: final reduce + scale + write ----
        {
            float sum = 1e-6f;
            #pragma unroll 4
            for (int c = 0; c < NCTAS; ++c)
                sum += __ldcg(&g_partial[c * SCOLS + tid]);  // L2 path (cross-SM coherent)
            sinv[tid] = rsqrtf(sum);
        }
        __syncthreads();
        const float4 inv = ((const float4*)sinv)[col4];
        #pragma unroll 4
        for (int r = r0; r < NROWS; r += ROWSTRIDE) {
            const int idx = r * DV + base;
            float4 v = __ldcs(&x4[idx]);           // last use: evict-first, still L2-hit
            float4 o;
            o.x = v.x * inv.x;
            o.y = v.y * inv.y;
            o.z = v.z * inv.z;
            o.w = v.w * inv.w;
            __stcs(&o4[idx], o);                   // streaming store: don't pollute L2
        }
        // Re-sync before next stripe: protects g_partial reuse and keeps the
        // chip in lockstep so stripe s+1's input doesn't evict stripe s's.
        if (s != NSTRIPES - 1) grid_barrier();
    }
}

extern "C" void kernel_launch(void* const* d_in, const int* in_sizes, int n_in,
                              void* d_out, int out_size) {
    const float* x = (const float*)d_in[0];
    float* out = (float*)d_out;
    colnorm_kernel<<<NCTAS, TPB>>>(x, out);
}

// round 8
// speedup vs baseline: 1.3697x; 1.3697x over previous
#include <cuda_runtime.h>

// Column-wise L2 normalization: u[d] = sum_n x[n,d]^2 + eps; out = x * rsqrt(u)
// x: [32768, 2048] fp32 row-major.
//
// Persistent kernel, 4 column stripes of 512 cols (64 MB each, fits GB300's
// ~126 MB L2). Per stripe: phase A reduces (input lands in L2), grid barrier,
// phase B re-reads (L2 hits) + writes with .cs streaming hints.
// R4 change: TPB 512->1024 (occ 25->50%) and 2-way parallel cross-CTA reduce.

#define NCTAS     148
#define TPB       1024
#define DV        512            // D/4 (float4 per full row)
#define NROWS     32768
#define NSTRIPES  4
#define SCOLS     512            // columns per stripe
#define SVEC      128            // float4 groups per stripe row
#define NPH       8              // row phases per CTA (TPB / SVEC)
#define ROWSTRIDE (NPH * NCTAS)  // 1184

#define CHALF     74             // NCTAS / 2 per reducing thread

__device__ float g_partial[NCTAS * SCOLS];   // per-CTA column partial sums
__device__ unsigned int g_bar_count;         // zero-initialized at load
__device__ unsigned int g_bar_gen;           // monotonically increasing (wrap-safe)

// Self-resetting grid barrier; all 148 CTAs are co-resident (1 CTA/SM).
__device__ __forceinline__ void grid_barrier() {
    __threadfence();
    __syncthreads();
    if (threadIdx.x == 0) {
        unsigned int target = *(volatile unsigned int*)&g_bar_gen + 1u;
        unsigned int arrived = atomicAdd(&g_bar_count, 1u);
        if (arrived == NCTAS - 1) {
            atomicExch(&g_bar_count, 0u);
            __threadfence();
            atomicAdd(&g_bar_gen, 1u);
        } else {
            while ((int)(*(volatile unsigned int*)&g_bar_gen - target) < 0)
                __nanosleep(64);
        }
        __threadfence();
    }
    __syncthreads();
}

__global__ __launch_bounds__(TPB, 1)
void colnorm_kernel(const float* __restrict__ x, float* __restrict__ out) {
    const int tid    = threadIdx.x;
    const int b      = blockIdx.x;
    const int col4   = tid & (SVEC - 1);       // float4 group within stripe
    const int rphase = tid >> 7;               // row phase (0..7)
    const int r0     = b + rphase * NCTAS;     // first row for this thread

    __shared__ float4 sred[NPH * SVEC];        // 16 KB: per-rowphase partials
    __shared__ float  spart[2 * SCOLS];        // 4 KB: 2-way final-reduce halves
    __shared__ float  sinv[SCOLS];             // 2 KB: rsqrt per stripe column

    const float4* __restrict__ x4 = (const float4*)x;
    float4* __restrict__       o4 = (float4*)out;

    for (int s = 0; s < NSTRIPES; ++s) {
        const int base = s * SVEC + col4;      // float4 index within a row

        // ---- Phase A: per-CTA column sum-of-squares over this stripe ----
        float4 acc = make_float4(0.f, 0.f, 0.f, 0.f);
        #pragma unroll 4
        for (int r = r0; r < NROWS; r += ROWSTRIDE) {
            float4 v = x4[r * DV + base];      // default .ca -> fills L2
            acc.x += v.x * v.x;
            acc.y += v.y * v.y;
            acc.z += v.z * v.z;
            acc.w += v.w * v.w;
        }
        sred[rphase * SVEC + col4] = acc;
        __syncthreads();
        if (tid < SCOLS) {
            // Fold the 8 row phases; tid indexes stripe-local column 0..511.
            const float* sf = (const float*)sred;
            float v = sf[tid];
            #pragma unroll
            for (int k = 1; k < NPH; ++k) v += sf[k * SCOLS + tid];
            g_partial[b * SCOLS + tid] = v;
        }
        grid_barrier();

        // ---- Final reduce across CTAs: 2 threads per column ----
        {
            const int col  = tid & (SCOLS - 1);
            const int half = tid >> 9;                  // 0 or 1
            const int c0   = half * CHALF;
            float sum = 0.f;
            #pragma unroll 8
            for (int c = 0; c < CHALF; ++c)
                sum += __ldcg(&g_partial[(c0 + c) * SCOLS + col]);
            spart[half * SCOLS + col] = sum;
        }
        __syncthreads();
        if (tid < SCOLS)
            sinv[tid] = rsqrtf(spart[tid] + spart[SCOLS + tid] + 1e-6f);
        __syncthreads();

        // ---- Phase B: scale + write (L2 hits on input, streaming stores) ----
        const float4 inv = ((const float4*)sinv)[col4];
        #pragma unroll 4
        for (int r = r0; r < NROWS; r += ROWSTRIDE) {
            const int idx = r * DV + base;
            float4 v = __ldcs(&x4[idx]);       // last use: evict-first, L2-hit
            float4 o;
            o.x = v.x * inv.x;
            o.y = v.y * inv.y;
            o.z = v.z * inv.z;
            o.w = v.w * inv.w;
            __stcs(&o4[idx], o);               // streaming store
        }
        // Keep chip in lockstep + protect g_partial reuse for next stripe.
        if (s != NSTRIPES - 1) grid_barrier();
    }
}

extern "C" void kernel_launch(void* const* d_in, const int* in_sizes, int n_in,
                              void* d_out, int out_size) {
    const float* x = (const float*)d_in[0];
    float* out = (float*)d_out;
    colnorm_kernel<<<NCTAS, TPB>>>(x, out);
}

// round 13
// speedup vs baseline: 1.5074x; 1.1005x over previous
#include <cuda_runtime.h>

// Column-wise L2 normalization: u[d] = sum_n x[n,d]^2 + eps; out = x * rsqrt(u)
// x: [32768, 2048] fp32 row-major.
//
// Persistent kernel, 4 column stripes of 512 cols (64 MB each, fits GB300's
// ~126 MB L2). Per stripe: phase A reduces (input lands in L2), grid barrier,
// phase B re-reads (L2 hits) + writes with .cs streaming hints.
// R8 change: explicit 8-deep load batching in both phases (MLP 4 -> 8/thread)
// to cut latency exposure; DRAM was only 47% busy at 49% occupancy.

#define NCTAS     148
#define TPB       1024
#define DV        512            // D/4 (float4 per full row)
#define NROWS     32768
#define NSTRIPES  4
#define SCOLS     512            // columns per stripe
#define SVEC      128            // float4 groups per stripe row
#define NPH       8              // row phases per CTA (TPB / SVEC)
#define ROWSTRIDE (NPH * NCTAS)  // 1184
#define BATCH     8              // loads in flight per thread

#define CHALF     74             // NCTAS / 2 per reducing thread

__device__ float g_partial[NCTAS * SCOLS];   // per-CTA column partial sums
__device__ unsigned int g_bar_count;         // zero-initialized at load
__device__ unsigned int g_bar_gen;           // monotonically increasing

// Self-resetting grid barrier; all 148 CTAs are co-resident (1 CTA/SM).
__device__ __forceinline__ void grid_barrier() {
    __threadfence();
    __syncthreads();
    if (threadIdx.x == 0) {
        unsigned int target = *(volatile unsigned int*)&g_bar_gen + 1u;
        unsigned int arrived = atomicAdd(&g_bar_count, 1u);
        if (arrived == NCTAS - 1) {
            atomicExch(&g_bar_count, 0u);
            __threadfence();
            atomicAdd(&g_bar_gen, 1u);
        } else {
            while ((int)(*(volatile unsigned int*)&g_bar_gen - target) < 0)
                __nanosleep(64);
        }
        __threadfence();
    }
    __syncthreads();
}

__global__ __launch_bounds__(TPB, 1)
void colnorm_kernel(const float* __restrict__ x, float* __restrict__ out) {
    const int tid    = threadIdx.x;
    const int b      = blockIdx.x;
    const int col4   = tid & (SVEC - 1);       // float4 group within stripe
    const int rphase = tid >> 7;               // row phase (0..7)
    const int r0     = b + rphase * NCTAS;     // first row for this thread

    __shared__ float4 sred[NPH * SVEC];        // 16 KB: per-rowphase partials
    __shared__ float  spart[2 * SCOLS];        // 4 KB: 2-way final-reduce halves
    __shared__ float  sinv[SCOLS];             // 2 KB: rsqrt per stripe column

    const float4* __restrict__ x4 = (const float4*)x;
    float4* __restrict__       o4 = (float4*)out;

    for (int s = 0; s < NSTRIPES; ++s) {
        const int base = s * SVEC + col4;      // float4 index within a row

        // ---- Phase A: per-CTA column sum-of-squares over this stripe ----
        // 8 loads issued back-to-back before any consumption -> MLP=8/thread.
        float4 acc = make_float4(0.f, 0.f, 0.f, 0.f);
        for (int r = r0; r < NROWS; r += BATCH * ROWSTRIDE) {
            float4 v[BATCH];
            #pragma unroll
            for (int j = 0; j < BATCH; ++j) {
                const int rr = r + j * ROWSTRIDE;
                v[j] = (rr < NROWS) ? x4[rr * DV + base]
                                    : make_float4(0.f, 0.f, 0.f, 0.f);
            }
            #pragma unroll
            for (int j = 0; j < BATCH; ++j) {
                acc.x += v[j].x * v[j].x;
                acc.y += v[j].y * v[j].y;
                acc.z += v[j].z * v[j].z;
                acc.w += v[j].w * v[j].w;
            }
        }
        sred[rphase * SVEC + col4] = acc;
        __syncthreads();
        if (tid < SCOLS) {
            // Fold the 8 row phases; tid = stripe-local column 0..511.
            const float* sf = (const float*)sred;
            float v = sf[tid];
            #pragma unroll
            for (int k = 1; k < NPH; ++k) v += sf[k * SCOLS + tid];
            g_partial[b * SCOLS + tid] = v;
        }
        grid_barrier();

        // ---- Final reduce across CTAs: 2 threads per column ----
        {
            const int col  = tid & (SCOLS - 1);
            const int half = tid >> 9;                  // 0 or 1
            const int c0   = half * CHALF;
            float sum = 0.f;
            #pragma unroll 8
            for (int c = 0; c < CHALF; ++c)
                sum += __ldcg(&g_partial[(c0 + c) * SCOLS + col]);
            spart[half * SCOLS + col] = sum;
        }
        __syncthreads();
        if (tid < SCOLS)
            sinv[tid] = rsqrtf(spart[tid] + spart[SCOLS + tid] + 1e-6f);
        __syncthreads();

        // ---- Phase B: scale + write (L2 hits on input, streaming stores) ----
        const float4 inv = ((const float4*)sinv)[col4];
        for (int r = r0; r < NROWS; r += BATCH * ROWSTRIDE) {
            float4 v[BATCH];
            #pragma unroll
            for (int j = 0; j < BATCH; ++j) {
                const int rr = r + j * ROWSTRIDE;
                if (rr < NROWS) v[j] = __ldcs(&x4[rr * DV + base]);
            }
            #pragma unroll
            for (int j = 0; j < BATCH; ++j) {
                const int rr = r + j * ROWSTRIDE;
                if (rr < NROWS) {
                    float4 o;
                    o.x = v[j].x * inv.x;
                    o.y = v[j].y * inv.y;
                    o.z = v[j].z * inv.z;
                    o.w = v[j].w * inv.w;
                    __stcs(&o4[rr * DV + base], o);
                }
            }
        }
        // Keep chip in lockstep + protect g_partial reuse for next stripe.
        if (s != NSTRIPES - 1) grid_barrier();
    }
}

extern "C" void kernel_launch(void* const* d_in, const int* in_sizes, int n_in,
                              void* d_out, int out_size) {
    const float* x = (const float*)d_in[0];
    float* out = (float*)d_out;
    colnorm_kernel<<<NCTAS, TPB>>>(x, out);
}

// round 15
// speedup vs baseline: 1.6365x; 1.0856x over previous
#include <cuda_runtime.h>

// Column-wise L2 normalization: u[d] = sum_n x[n,d]^2 + eps; out = x * rsqrt(u)
// x: [32768, 2048] fp32 row-major.
//
// Persistent kernel, 4 column stripes of 512 cols (64 MB, fits ~126 MB L2).
// Per stripe: phase A reduce (input lands in L2), ONE grid barrier, final
// reduce, phase B re-read (L2 hits) + .cs streaming stores.
// R13/R14: (1) g_partial double-buffered by stripe parity -> 7 barriers
// become 4; (2) constant-trip-count load batching (3x8 + 3 + 1 predicated)
// so MLP=8 survives the 64-reg cap. (R14 = R13 resubmit; infra failure.)

#define NCTAS     148
#define TPB       1024
#define DV        512            // D/4 (float4 per full row)
#define NROWS     32768
#define NSTRIPES  4
#define SCOLS     512            // columns per stripe
#define SVEC      128            // float4 groups per stripe row
#define NPH       8              // row phases per CTA (TPB / SVEC)
#define ROWSTRIDE (NPH * NCTAS)  // 1184
#define STEP      (ROWSTRIDE * DV)
#define CHALF     74             // NCTAS / 2 per reducing thread
#define R27LIM    800            // r0 < 800 <=> iteration k=27 is in-bounds

__device__ float g_partial[2][NCTAS * SCOLS]; // double-buffered partials
__device__ unsigned int g_bar_count;
__device__ unsigned int g_bar_gen;

// Self-resetting grid barrier; all 148 CTAs co-resident (1 CTA/SM).
__device__ __forceinline__ void grid_barrier() {
    __threadfence();
    __syncthreads();
    if (threadIdx.x == 0) {
        unsigned int target = *(volatile unsigned int*)&g_bar_gen + 1u;
        unsigned int arrived = atomicAdd(&g_bar_count, 1u);
        if (arrived == NCTAS - 1) {
            atomicExch(&g_bar_count, 0u);
            __threadfence();
            atomicAdd(&g_bar_gen, 1u);
        } else {
            while ((int)(*(volatile unsigned int*)&g_bar_gen - target) < 0)
                __nanosleep(64);
        }
        __threadfence();
    }
    __syncthreads();
}

__global__ __launch_bounds__(TPB, 1)
void colnorm_kernel(const float* __restrict__ x, float* __restrict__ out) {
    const int tid    = threadIdx.x;
    const int b      = blockIdx.x;
    const int col4   = tid & (SVEC - 1);       // float4 group within stripe
    const int rphase = tid >> 7;               // row phase (0..7)
    const int r0     = b + rphase * NCTAS;     // first row for this thread
    const bool has27 = (r0 < R27LIM);

    __shared__ float4 sred[NPH * SVEC];        // 16 KB: per-rowphase partials
    __shared__ float  spart[2 * SCOLS];        // 4 KB: 2-way reduce halves
    __shared__ float  sinv[SCOLS];             // 2 KB: rsqrt per stripe column

    const float4* __restrict__ x4 = (const float4*)x;
    float4* __restrict__       o4 = (float4*)out;

    for (int s = 0; s < NSTRIPES; ++s) {
        const int base  = s * SVEC + col4;     // float4 index within a row
        const int idx0  = r0 * DV + base;
        float* __restrict__ gp = g_partial[s & 1];

        // ---- Phase A: per-CTA column sum-of-squares over this stripe ----
        // 27 unconditional iterations (3 batches of 8 + 3) + 1 predicated.
        float4 acc = make_float4(0.f, 0.f, 0.f, 0.f);
        {
            int idx = idx0;
            #pragma unroll
            for (int t = 0; t < 3; ++t) {
                float4 v[8];
                #pragma unroll
                for (int j = 0; j < 8; ++j) v[j] = x4[idx + j * STEP];
                #pragma unroll
                for (int j = 0; j < 8; ++j) {
                    acc.x += v[j].x * v[j].x;
                    acc.y += v[j].y * v[j].y;
                    acc.z += v[j].z * v[j].z;
                    acc.w += v[j].w * v[j].w;
                }
                idx += 8 * STEP;
            }
            float4 v[4];
            v[0] = x4[idx];
            v[1] = x4[idx + STEP];
            v[2] = x4[idx + 2 * STEP];
            v[3] = has27 ? x4[idx + 3 * STEP] : make_float4(0.f, 0.f, 0.f, 0.f);
            #pragma unroll
            for (int j = 0; j < 4; ++j) {
                acc.x += v[j].x * v[j].x;
                acc.y += v[j].y * v[j].y;
                acc.z += v[j].z * v[j].z;
                acc.w += v[j].w * v[j].w;
            }
        }
        sred[rphase * SVEC + col4] = acc;
        __syncthreads();
        if (tid < SCOLS) {
            const float* sf = (const float*)sred;
            float v = sf[tid];
            #pragma unroll
            for (int k = 1; k < NPH; ++k) v += sf[k * SCOLS + tid];
            gp[b * SCOLS + tid] = v;
        }
        grid_barrier();   // the ONLY barrier per stripe

        // ---- Final reduce across CTAs: 2 threads per column ----
        {
            const int col  = tid & (SCOLS - 1);
            const int half = tid >> 9;                  // 0 or 1
            const int c0   = half * CHALF;
            float sum = 0.f;
            #pragma unroll 8
            for (int c = 0; c < CHALF; ++c)
                sum += __ldcg(&gp[(c0 + c) * SCOLS + col]);
            spart[half * SCOLS + col] = sum;
        }
        __syncthreads();
        if (tid < SCOLS)
            sinv[tid] = rsqrtf(spart[tid] + spart[SCOLS + tid] + 1e-6f);
        __syncthreads();

        // ---- Phase B: scale + write (L2 hits on input, streaming stores) ----
        const float4 inv = ((const float4*)sinv)[col4];
        {
            int idx = idx0;
            #pragma unroll
            for (int t = 0; t < 3; ++t) {
                float4 v[8];
                #pragma unroll
                for (int j = 0; j < 8; ++j) v[j] = __ldcs(&x4[idx + j * STEP]);
                #pragma unroll
                for (int j = 0; j < 8; ++j) {
                    float4 o;
                    o.x = v[j].x * inv.x;
                    o.y = v[j].y * inv.y;
                    o.z = v[j].z * inv.z;
                    o.w = v[j].w * inv.w;
                    __stcs(&o4[idx + j * STEP], o);
                }
                idx += 8 * STEP;
            }
            float4 v[4];
            v[0] = __ldcs(&x4[idx]);
            v[1] = __ldcs(&x4[idx + STEP]);
            v[2] = __ldcs(&x4[idx + 2 * STEP]);
            if (has27) v[3] = __ldcs(&x4[idx + 3 * STEP]);
            #pragma unroll
            for (int j = 0; j < 3; ++j) {
                float4 o;
                o.x = v[j].x * inv.x;
                o.y = v[j].y * inv.y;
                o.z = v[j].z * inv.z;
                o.w = v[j].w * inv.w;
                __stcs(&o4[idx + j * STEP], o);
            }
            if (has27) {
                float4 o;
                o.x = v[3].x * inv.x;
                o.y = v[3].y * inv.y;
                o.z = v[3].z * inv.z;
                o.w = v[3].w * inv.w;
                __stcs(&o4[idx + 3 * STEP], o);
            }
        }
        // No inter-stripe barrier: next stripe writes the OTHER g_partial
        // buffer, and a full barrier separates any CTA's last read of a
        // buffer from any CTA's next write of that buffer.
    }
}

extern "C" void kernel_launch(void* const* d_in, const int* in_sizes, int n_in,
                              void* d_out, int out_size) {
    const float* x = (const float*)d_in[0];
    float* out = (float*)d_out;
    colnorm_kernel<<<NCTAS, TPB>>>(x, out);
}